// round 4
// baseline (speedup 1.0000x reference)
#include <cuda_runtime.h>
#include <cuda_bf16.h>
#include <math.h>
#include <math_constants.h>
#include <stdint.h>

// ---------------------------------------------------------------------------
// Problem constants
// ---------------------------------------------------------------------------
#define B        2
#define NQ       2048
#define NCTX     512
#define F        1024
#define MID      1024
#define NHEAD    16
#define HDIM     64
#define ROWS_X   (B * NQ)      // 4096
#define ROWS_C   (B * NCTX)    // 1024

// ---------------------------------------------------------------------------
// Scratch (device globals)
// ---------------------------------------------------------------------------
__device__ __nv_bfloat16 g_xn [ROWS_X * F];
__device__ __nv_bfloat16 g_cn [ROWS_X * F];
__device__ __nv_bfloat16 g_q  [ROWS_X * MID];
__device__ __nv_bfloat16 g_kv [ROWS_X * 2 * MID];
__device__ __nv_bfloat16 g_ao [ROWS_X * MID];
__device__ float         g_x1 [ROWS_X * F];
__device__ float         g_tbl[2 * NHEAD * 4096];   // [0]=self, [1]=cross
__device__ __nv_bfloat16 g_wtq  [MID * F];
__device__ __nv_bfloat16 g_wtkv [2 * MID * F];
__device__ __nv_bfloat16 g_wto  [F * MID];
__device__ __nv_bfloat16 g_wtq2 [MID * F];
__device__ __nv_bfloat16 g_wtkv2[2 * MID * F];
__device__ __nv_bfloat16 g_wto2 [F * MID];

// ---------------------------------------------------------------------------
// PTX helpers
// ---------------------------------------------------------------------------
__device__ __forceinline__ uint32_t su32(const void* p) {
    return (uint32_t)__cvta_generic_to_shared(p);
}
__device__ __forceinline__ void cp16(uint32_t dst, const void* src) {
    asm volatile("cp.async.cg.shared.global [%0], [%1], 16;" :: "r"(dst), "l"(src));
}
__device__ __forceinline__ void cp_commit() {
    asm volatile("cp.async.commit_group;");
}
template<int N> __device__ __forceinline__ void cp_wait() {
    asm volatile("cp.async.wait_group %0;" :: "n"(N));
}
__device__ __forceinline__ void ldm_x4(uint32_t r[4], uint32_t addr) {
    asm volatile("ldmatrix.sync.aligned.m8n8.x4.shared.b16 {%0,%1,%2,%3}, [%4];"
                 : "=r"(r[0]), "=r"(r[1]), "=r"(r[2]), "=r"(r[3]) : "r"(addr));
}
__device__ __forceinline__ void ldm_x4_t(uint32_t r[4], uint32_t addr) {
    asm volatile("ldmatrix.sync.aligned.m8n8.x4.trans.shared.b16 {%0,%1,%2,%3}, [%4];"
                 : "=r"(r[0]), "=r"(r[1]), "=r"(r[2]), "=r"(r[3]) : "r"(addr));
}
__device__ __forceinline__ void mma_bf16(float c[4], const uint32_t a[4], const uint32_t b[2]) {
    asm volatile(
        "mma.sync.aligned.m16n8k16.row.col.f32.bf16.bf16.f32 "
        "{%0,%1,%2,%3}, {%4,%5,%6,%7}, {%8,%9}, {%0,%1,%2,%3};\n"
        : "+f"(c[0]), "+f"(c[1]), "+f"(c[2]), "+f"(c[3])
        : "r"(a[0]), "r"(a[1]), "r"(a[2]), "r"(a[3]), "r"(b[0]), "r"(b[1]));
}
__device__ __forceinline__ uint32_t packbf(float lo, float hi) {
    __nv_bfloat162 t = __floats2bfloat162_rn(lo, hi);
    return *reinterpret_cast<uint32_t*>(&t);
}

// ---------------------------------------------------------------------------
// LayerNorm helpers
// ---------------------------------------------------------------------------
__device__ __forceinline__ void ln_stats(float4 v, float* red, int tid,
                                         float& mean, float& rs)
{
    float s = v.x + v.y + v.z + v.w;
    #pragma unroll
    for (int o = 16; o > 0; o >>= 1) s += __shfl_xor_sync(0xffffffffu, s, o);
    if ((tid & 31) == 0) red[tid >> 5] = s;
    __syncthreads();
    float tot = 0.f;
    #pragma unroll
    for (int i = 0; i < 8; i++) tot += red[i];
    mean = tot * (1.0f / F);

    float dx = v.x - mean, dy = v.y - mean, dz = v.z - mean, dw = v.w - mean;
    float sq = dx * dx + dy * dy + dz * dz + dw * dw;
    #pragma unroll
    for (int o = 16; o > 0; o >>= 1) sq += __shfl_xor_sync(0xffffffffu, sq, o);
    __syncthreads();
    if ((tid & 31) == 0) red[tid >> 5] = sq;
    __syncthreads();
    float tsq = 0.f;
    #pragma unroll
    for (int i = 0; i < 8; i++) tsq += red[i];
    rs = rsqrtf(tsq * (1.0f / F) + 1e-5f);
}

__device__ __forceinline__ void ln_store(float4 v, float mean, float rs,
    const float* __restrict__ g, const float* __restrict__ bta,
    __nv_bfloat16* __restrict__ out, int row, int tid)
{
    const float4 gv = ((const float4*)g)[tid];
    const float4 bv = ((const float4*)bta)[tid];
    float dx = v.x - mean, dy = v.y - mean, dz = v.z - mean, dw = v.w - mean;
    __nv_bfloat162 p0 = __floats2bfloat162_rn(dx * rs * gv.x + bv.x, dy * rs * gv.y + bv.y);
    __nv_bfloat162 p1 = __floats2bfloat162_rn(dz * rs * gv.z + bv.z, dw * rs * gv.w + bv.w);
    uint2 u = make_uint2(*(uint32_t*)&p0, *(uint32_t*)&p1);
    *(uint2*)(out + (size_t)row * F + tid * 4) = u;
}

__global__ __launch_bounds__(256) void ln_kernel(
    const float* __restrict__ x, const float* __restrict__ g,
    const float* __restrict__ bta, __nv_bfloat16* __restrict__ out)
{
    __shared__ float red[8];
    const int row = blockIdx.x, tid = threadIdx.x;
    float4 v = ((const float4*)(x + (size_t)row * F))[tid];
    float mean, rs;
    ln_stats(v, red, tid, mean, rs);
    ln_store(v, mean, rs, g, bta, out, row, tid);
}

// dual-output LN: same x row, two gamma/beta sets, one read + shared stats
__global__ __launch_bounds__(256) void ln2_kernel(
    const float* __restrict__ x,
    const float* __restrict__ g1, const float* __restrict__ b1, __nv_bfloat16* __restrict__ o1,
    const float* __restrict__ g2, const float* __restrict__ b2, __nv_bfloat16* __restrict__ o2)
{
    __shared__ float red[8];
    const int row = blockIdx.x, tid = threadIdx.x;
    float4 v = ((const float4*)(x + (size_t)row * F))[tid];
    float mean, rs;
    ln_stats(v, red, tid, mean, rs);
    ln_store(v, mean, rs, g1, b1, o1, row, tid);
    ln_store(v, mean, rs, g2, b2, o2, row, tid);
}

// ---------------------------------------------------------------------------
// Both rel-pos bias tables in one launch
// ---------------------------------------------------------------------------
__global__ __launch_bounds__(256) void bias2_kernel(
    const float* __restrict__ e0, const float* __restrict__ e1,
    float* __restrict__ tbl)
{
    const int idx = blockIdx.x * 256 + threadIdx.x;   // 0..131071
    const float* emb = (idx < 65536) ? e0 : e1;
    const int li = idx & 65535;
    const int h = li >> 12;
    const int p = li & 4095;
    const int rel = p - 2048;
    const int retv = (rel >= 0) ? 16 : 0;
    const int na = (rel < 0) ? -rel : rel;
    int bucket;
    if (na < 8) {
        bucket = retv + na;
    } else {
        float t = logf((float)na * 0.125f) / 2.7725887f;   // log(16)
        int vl = 8 + (int)(t * 8.0f);
        bucket = retv + min(vl, 15);
    }
    tbl[idx] = emb[bucket * NHEAD + h];
}

// ---------------------------------------------------------------------------
// All 6 weight transposes in one segmented launch.
// W[K][N] fp32 -> Wt[N][K] bf16, 32x32 tiles, 32x8 threads.
// ---------------------------------------------------------------------------
struct WDesc {
    const float* W[6];
    __nv_bfloat16* Wt[6];
    int K[6], N[6];
    int start[7];
};

__global__ __launch_bounds__(256) void wtrans_all_kernel(WDesc d)
{
    __shared__ float t[32][33];
    const int bid = blockIdx.x;
    int s = 0;
    #pragma unroll
    for (int i = 1; i < 6; i++) if (bid >= d.start[i]) s = i;

    const float* W = d.W[s];
    __nv_bfloat16* Wt = d.Wt[s];
    const int K = d.K[s], N = d.N[s];
    const int bi = bid - d.start[s];
    const int nbx = N >> 5;
    const int n0 = (bi % nbx) * 32;
    const int k0 = (bi / nbx) * 32;

    const int tx = threadIdx.x, ty = threadIdx.y;
    #pragma unroll
    for (int i = 0; i < 4; i++)
        t[ty + 8 * i][tx] = W[(size_t)(k0 + ty + 8 * i) * N + n0 + tx];
    __syncthreads();
    #pragma unroll
    for (int i = 0; i < 4; i++)
        Wt[(size_t)(n0 + ty + 8 * i) * K + k0 + tx] = __float2bfloat16(t[tx][ty + 8 * i]);
}

// ---------------------------------------------------------------------------
// bf16 GEMM: C[M,N] = A[M,K] @ Bt[N,K]^T (+bias) (+res)
// 128x128 tile, Ktile 32, 8 warps, 3-stage cp.async ring (dynamic smem),
// ldmatrix fragments. Row stride 40 bf16 => conflict-free ldmatrix.
// ---------------------------------------------------------------------------
#define GSTAGE_ELEM (128 * 40)
#define GEMM_SMEM   (3 * 2 * GSTAGE_ELEM * 2)   // 61440 bytes

template<bool OBF>
__global__ __launch_bounds__(256) void gemm_bf16(
    const __nv_bfloat16* __restrict__ A, const __nv_bfloat16* __restrict__ Bt,
    void* __restrict__ Cv, int M, int N, int K,
    const float* __restrict__ bias, const float* __restrict__ res)
{
    extern __shared__ __nv_bfloat16 dsm[];
    __nv_bfloat16* As = dsm;
    __nv_bfloat16* Bs = dsm + 3 * GSTAGE_ELEM;

    const int tid = threadIdx.x;
    const int warp = tid >> 5, lane = tid & 31;
    const int q = lane >> 2, cq = lane & 3;
    const int wm = (warp >> 2) * 64, wn = (warp & 3) * 32;
    const int bm = blockIdx.y * 128, bn = blockIdx.x * 128;

    float acc[4][4][4];
    #pragma unroll
    for (int mt = 0; mt < 4; mt++)
        #pragma unroll
        for (int nt = 0; nt < 4; nt++)
            #pragma unroll
            for (int e = 0; e < 4; e++) acc[mt][nt][e] = 0.f;

    const int lr = tid >> 2;
    const int lc = (tid & 3) * 8;

    auto load_tile = [&](int kt, int st) {
        const __nv_bfloat16* Ag = A + (size_t)bm * K + kt * 32 + lc;
        const __nv_bfloat16* Bg = Bt + (size_t)bn * K + kt * 32 + lc;
        __nv_bfloat16* as = As + st * GSTAGE_ELEM;
        __nv_bfloat16* bs = Bs + st * GSTAGE_ELEM;
        cp16(su32(as + lr * 40 + lc),        Ag + (size_t)lr * K);
        cp16(su32(as + (lr + 64) * 40 + lc), Ag + (size_t)(lr + 64) * K);
        cp16(su32(bs + lr * 40 + lc),        Bg + (size_t)lr * K);
        cp16(su32(bs + (lr + 64) * 40 + lc), Bg + (size_t)(lr + 64) * K);
    };

    const int KT = K / 32;
    load_tile(0, 0); cp_commit();
    load_tile(1, 1); cp_commit();

    for (int kt = 0; kt < KT; kt++) {
        if (kt + 2 < KT) { load_tile(kt + 2, (kt + 2) % 3); cp_commit(); cp_wait<2>(); }
        else if (kt + 1 < KT) cp_wait<1>();
        else cp_wait<0>();
        __syncthreads();

        const __nv_bfloat16* as = As + (kt % 3) * GSTAGE_ELEM;
        const __nv_bfloat16* bs = Bs + (kt % 3) * GSTAGE_ELEM;
        #pragma unroll
        for (int ks = 0; ks < 2; ks++) {
            uint32_t af[4][4], bfr[2][4];
            #pragma unroll
            for (int mt = 0; mt < 4; mt++) {
                const int row = wm + mt * 16 + ((lane >> 3) & 1) * 8 + (lane & 7);
                const int col = ks * 16 + (lane >> 4) * 8;
                ldm_x4(af[mt], su32(as + row * 40 + col));
            }
            #pragma unroll
            for (int pn = 0; pn < 2; pn++) {
                const int row = wn + pn * 16 + (lane >> 4) * 8 + (lane & 7);
                const int col = ks * 16 + ((lane >> 3) & 1) * 8;
                ldm_x4(bfr[pn], su32(bs + row * 40 + col));
            }
            #pragma unroll
            for (int mt = 0; mt < 4; mt++)
                #pragma unroll
                for (int nt = 0; nt < 4; nt++)
                    mma_bf16(acc[mt][nt], af[mt], &bfr[nt >> 1][(nt & 1) * 2]);
        }
        __syncthreads();
    }

    #pragma unroll
    for (int mt = 0; mt < 4; mt++) {
        #pragma unroll
        for (int nt = 0; nt < 4; nt++) {
            const int c0 = bn + wn + nt * 8 + 2 * cq;
            #pragma unroll
            for (int half = 0; half < 2; half++) {
                const int row = bm + wm + mt * 16 + q + half * 8;
                float v0 = acc[mt][nt][half * 2 + 0];
                float v1 = acc[mt][nt][half * 2 + 1];
                const size_t base = (size_t)row * N + c0;
                if (OBF) {
                    __nv_bfloat16* C = (__nv_bfloat16*)Cv;
                    *(uint32_t*)(C + base) = packbf(v0, v1);
                } else {
                    float* C = (float*)Cv;
                    if (bias) { v0 += bias[c0]; v1 += bias[c0 + 1]; }
                    if (res)  { v0 += res[base]; v1 += res[base + 1]; }
                    *(float2*)(C + base) = make_float2(v0, v1);
                }
            }
        }
    }
}

// ---------------------------------------------------------------------------
// Flash attention, bf16 MMA. Block = 256 thr (8 warps) = one (b,h,128-q tile).
// Warp w owns q rows [w*16, w*16+16). K/V chunks of 64 j, double-buffered.
// tbl is the per-pass table base; per-head offset h*4096 applied inside.
// ---------------------------------------------------------------------------
__global__ __launch_bounds__(256) void attn_bf16(
    const __nv_bfloat16* __restrict__ qb, const __nv_bfloat16* __restrict__ kvb,
    __nv_bfloat16* __restrict__ ob, const float* __restrict__ tbl,
    int n, int m, int mnoff)
{
    __shared__ __nv_bfloat16 Ks[2][64 * 72];
    __shared__ __nv_bfloat16 Vs[2][64 * 72];
    __shared__ float sb[192];

    const int tid = threadIdx.x;
    const int warp = tid >> 5, lane = tid & 31;
    const int q = lane >> 2, cq = lane & 3;
    const int b = blockIdx.z, h = blockIdx.y;
    const int q0 = blockIdx.x * 128;
    const int r0l = warp * 16 + q;     // 0..127
    const int r1l = r0l + 8;
    const float* tblh = tbl + h * 4096;

    uint32_t qf[4][4];
    {
        const __nv_bfloat16* qr0 = qb + (size_t)(b * n + q0 + r0l) * MID + h * HDIM;
        const __nv_bfloat16* qr1 = qr0 + 8 * (size_t)MID;
        #pragma unroll
        for (int ks = 0; ks < 4; ks++) {
            qf[ks][0] = *(const uint32_t*)(qr0 + ks * 16 + cq * 2);
            qf[ks][1] = *(const uint32_t*)(qr1 + ks * 16 + cq * 2);
            qf[ks][2] = *(const uint32_t*)(qr0 + ks * 16 + cq * 2 + 8);
            qf[ks][3] = *(const uint32_t*)(qr1 + ks * 16 + cq * 2 + 8);
        }
    }

    float o[8][4];
    #pragma unroll
    for (int dt = 0; dt < 8; dt++)
        #pragma unroll
        for (int e = 0; e < 4; e++) o[dt][e] = 0.f;
    float mrun0 = -CUDART_INF_F, mrun1 = -CUDART_INF_F;
    float lrun0 = 0.f, lrun1 = 0.f;

    const __nv_bfloat16* kvbase = kvb + (size_t)(b * m) * (2 * MID) + h * HDIM;
    const int lr0 = tid >> 3;          // 0..31
    const int lc8 = (tid & 7) * 8;

    auto load_kv = [&](int c, int bi) {
        const __nv_bfloat16* kg = kvbase + (size_t)(c * 64) * (2 * MID);
        #pragma unroll
        for (int i = 0; i < 2; i++) {
            const int r = lr0 + i * 32;
            cp16(su32(&Ks[bi][r * 72 + lc8]), kg + (size_t)r * (2 * MID) + lc8);
            cp16(su32(&Vs[bi][r * 72 + lc8]), kg + MID + (size_t)r * (2 * MID) + lc8);
        }
    };

    const int C = m / 64;
    load_kv(0, 0); cp_commit();

    for (int c = 0; c < C; c++) {
        if (c + 1 < C) { load_kv(c + 1, (c + 1) & 1); cp_commit(); cp_wait<1>(); }
        else           { cp_wait<0>(); }
        __syncthreads();

        // bias slice: sb[t] = bias at (j - r) = t - 127, t in [0,190]
        const int base = 2048 + c * 64 - q0 - mnoff;
        if (tid < 191) sb[tid] = tblh[base + tid - 127];
        __syncthreads();

        const __nv_bfloat16* ks_b = Ks[c & 1];
        const __nv_bfloat16* vs_b = Vs[c & 1];

        // ---- S = Q @ K^T ----
        float s[8][4];
        #pragma unroll
        for (int nt = 0; nt < 8; nt++)
            #pragma unroll
            for (int e = 0; e < 4; e++) s[nt][e] = 0.f;

        #pragma unroll
        for (int ks = 0; ks < 4; ks++) {
            uint32_t bfr[4][4];
            #pragma unroll
            for (int pn = 0; pn < 4; pn++) {
                const int row = pn * 16 + (lane >> 4) * 8 + (lane & 7);
                const int col = ks * 16 + ((lane >> 3) & 1) * 8;
                ldm_x4(bfr[pn], su32(ks_b + row * 72 + col));
            }
            #pragma unroll
            for (int nt = 0; nt < 8; nt++)
                mma_bf16(s[nt], qf[ks], &bfr[nt >> 1][(nt & 1) * 2]);
        }

        // ---- bias + scale + row max ----
        float cmax0 = -CUDART_INF_F, cmax1 = -CUDART_INF_F;
        #pragma unroll
        for (int nt = 0; nt < 8; nt++) {
            #pragma unroll
            for (int e = 0; e < 2; e++) {
                const int jl = nt * 8 + 2 * cq + e;
                s[nt][e]     = (s[nt][e]     + sb[jl - r0l + 127]) * 0.125f;
                s[nt][2 + e] = (s[nt][2 + e] + sb[jl - r1l + 127]) * 0.125f;
                cmax0 = fmaxf(cmax0, s[nt][e]);
                cmax1 = fmaxf(cmax1, s[nt][2 + e]);
            }
        }
        cmax0 = fmaxf(cmax0, __shfl_xor_sync(0xffffffffu, cmax0, 1));
        cmax0 = fmaxf(cmax0, __shfl_xor_sync(0xffffffffu, cmax0, 2));
        cmax1 = fmaxf(cmax1, __shfl_xor_sync(0xffffffffu, cmax1, 1));
        cmax1 = fmaxf(cmax1, __shfl_xor_sync(0xffffffffu, cmax1, 2));

        const float mn0 = fmaxf(mrun0, cmax0);
        const float mn1 = fmaxf(mrun1, cmax1);
        const float al0 = __expf(mrun0 - mn0);
        const float al1 = __expf(mrun1 - mn1);

        float ps0 = 0.f, ps1 = 0.f;
        #pragma unroll
        for (int nt = 0; nt < 8; nt++) {
            #pragma unroll
            for (int e = 0; e < 2; e++) {
                s[nt][e]     = __expf(s[nt][e]     - mn0);
                s[nt][2 + e] = __expf(s[nt][2 + e] - mn1);
                ps0 += s[nt][e];
                ps1 += s[nt][2 + e];
            }
        }
        ps0 += __shfl_xor_sync(0xffffffffu, ps0, 1);
        ps0 += __shfl_xor_sync(0xffffffffu, ps0, 2);
        ps1 += __shfl_xor_sync(0xffffffffu, ps1, 1);
        ps1 += __shfl_xor_sync(0xffffffffu, ps1, 2);

        lrun0 = lrun0 * al0 + ps0;
        lrun1 = lrun1 * al1 + ps1;
        #pragma unroll
        for (int dt = 0; dt < 8; dt++) {
            o[dt][0] *= al0; o[dt][1] *= al0;
            o[dt][2] *= al1; o[dt][3] *= al1;
        }
        mrun0 = mn0; mrun1 = mn1;

        // ---- O += P @ V ----
        #pragma unroll
        for (int kt = 0; kt < 4; kt++) {
            uint32_t ap[4];
            ap[0] = packbf(s[2 * kt][0],     s[2 * kt][1]);
            ap[1] = packbf(s[2 * kt][2],     s[2 * kt][3]);
            ap[2] = packbf(s[2 * kt + 1][0], s[2 * kt + 1][1]);
            ap[3] = packbf(s[2 * kt + 1][2], s[2 * kt + 1][3]);
            #pragma unroll
            for (int dp = 0; dp < 4; dp++) {
                uint32_t bv[4];
                const int row = kt * 16 + ((lane >> 3) & 1) * 8 + (lane & 7);
                const int col = dp * 16 + (lane >> 4) * 8;
                ldm_x4_t(bv, su32(vs_b + row * 72 + col));
                mma_bf16(o[2 * dp],     ap, &bv[0]);
                mma_bf16(o[2 * dp + 1], ap, &bv[2]);
            }
        }
        __syncthreads();
    }

    const float inv0 = 1.0f / lrun0;
    const float inv1 = 1.0f / lrun1;
    __nv_bfloat16* or0 = ob + (size_t)(b * n + q0 + r0l) * MID + h * HDIM;
    __nv_bfloat16* or1 = ob + (size_t)(b * n + q0 + r1l) * MID + h * HDIM;
    #pragma unroll
    for (int dt = 0; dt < 8; dt++) {
        const int cc = dt * 8 + 2 * cq;
        *(uint32_t*)(or0 + cc) = packbf(o[dt][0] * inv0, o[dt][1] * inv0);
        *(uint32_t*)(or1 + cc) = packbf(o[dt][2] * inv1, o[dt][3] * inv1);
    }
}

// ---------------------------------------------------------------------------
// Launch
// ---------------------------------------------------------------------------
extern "C" void kernel_launch(void* const* d_in, const int* in_sizes, int n_in,
                              void* d_out, int out_size)
{
    (void)in_sizes; (void)n_in; (void)out_size;

    const float* x       = (const float*)d_in[0];
    const float* ctx     = (const float*)d_in[1];
    const float* sa_ng   = (const float*)d_in[2];
    const float* sa_nb   = (const float*)d_in[3];
    const float* sa_ncg  = (const float*)d_in[4];
    const float* sa_ncb  = (const float*)d_in[5];
    const float* sa_wq   = (const float*)d_in[6];
    const float* sa_wkv  = (const float*)d_in[7];
    const float* sa_wo   = (const float*)d_in[8];
    const float* sa_bo   = (const float*)d_in[9];
    const float* sa_rel  = (const float*)d_in[10];
    const float* ca_ng   = (const float*)d_in[11];
    const float* ca_nb   = (const float*)d_in[12];
    const float* ca_ncg  = (const float*)d_in[13];
    const float* ca_ncb  = (const float*)d_in[14];
    const float* ca_wq   = (const float*)d_in[15];
    const float* ca_wkv  = (const float*)d_in[16];
    const float* ca_wo   = (const float*)d_in[17];
    const float* ca_bo   = (const float*)d_in[18];
    const float* ca_rel  = (const float*)d_in[19];
    float* out = (float*)d_out;

    __nv_bfloat16 *xn, *cn, *q, *kv, *ao, *wtq, *wtkv, *wto, *wtq2, *wtkv2, *wto2;
    float *x1, *tbl;
    cudaGetSymbolAddress((void**)&xn,    g_xn);
    cudaGetSymbolAddress((void**)&cn,    g_cn);
    cudaGetSymbolAddress((void**)&q,     g_q);
    cudaGetSymbolAddress((void**)&kv,    g_kv);
    cudaGetSymbolAddress((void**)&ao,    g_ao);
    cudaGetSymbolAddress((void**)&x1,    g_x1);
    cudaGetSymbolAddress((void**)&tbl,   g_tbl);
    cudaGetSymbolAddress((void**)&wtq,   g_wtq);
    cudaGetSymbolAddress((void**)&wtkv,  g_wtkv);
    cudaGetSymbolAddress((void**)&wto,   g_wto);
    cudaGetSymbolAddress((void**)&wtq2,  g_wtq2);
    cudaGetSymbolAddress((void**)&wtkv2, g_wtkv2);
    cudaGetSymbolAddress((void**)&wto2,  g_wto2);

    cudaFuncSetAttribute(gemm_bf16<true>,  cudaFuncAttributeMaxDynamicSharedMemorySize, GEMM_SMEM);
    cudaFuncSetAttribute(gemm_bf16<false>, cudaFuncAttributeMaxDynamicSharedMemorySize, GEMM_SMEM);

    // ---- fused prep: 6 weight transposes + both bias tables ----
    WDesc wd;
    wd.W[0] = sa_wq;  wd.Wt[0] = wtq;   wd.K[0] = F;   wd.N[0] = MID;
    wd.W[1] = sa_wkv; wd.Wt[1] = wtkv;  wd.K[1] = F;   wd.N[1] = 2 * MID;
    wd.W[2] = sa_wo;  wd.Wt[2] = wto;   wd.K[2] = MID; wd.N[2] = F;
    wd.W[3] = ca_wq;  wd.Wt[3] = wtq2;  wd.K[3] = F;   wd.N[3] = MID;
    wd.W[4] = ca_wkv; wd.Wt[4] = wtkv2; wd.K[4] = F;   wd.N[4] = 2 * MID;
    wd.W[5] = ca_wo;  wd.Wt[5] = wto2;  wd.K[5] = MID; wd.N[5] = F;
    int cum = 0;
    for (int i = 0; i < 6; i++) {
        wd.start[i] = cum;
        cum += (wd.N[i] / 32) * (wd.K[i] / 32);
    }
    wd.start[6] = cum;
    wtrans_all_kernel<<<cum, dim3(32, 8)>>>(wd);
    bias2_kernel<<<512, 256>>>(sa_rel, ca_rel, tbl);

    // ---------------- self-attention ----------------
    ln2_kernel<<<ROWS_X, 256>>>(x, sa_ng, sa_nb, xn, sa_ncg, sa_ncb, cn);
    gemm_bf16<true ><<<dim3(MID / 128,     ROWS_X / 128), 256, GEMM_SMEM>>>(xn, wtq,  q,  ROWS_X, MID,     F, nullptr, nullptr);
    gemm_bf16<true ><<<dim3(2 * MID / 128, ROWS_X / 128), 256, GEMM_SMEM>>>(cn, wtkv, kv, ROWS_X, 2 * MID, F, nullptr, nullptr);
    attn_bf16<<<dim3(NQ / 128, NHEAD, B), 256>>>(q, kv, ao, tbl, NQ, NQ, 0);
    gemm_bf16<false><<<dim3(F / 128, ROWS_X / 128), 256, GEMM_SMEM>>>(ao, wto, x1, ROWS_X, F, MID, sa_bo, x);

    // ---------------- cross-attention ----------------
    ln_kernel<<<ROWS_X, 256>>>(x1,  ca_ng,  ca_nb,  xn);
    ln_kernel<<<ROWS_C, 256>>>(ctx, ca_ncg, ca_ncb, cn);
    gemm_bf16<true ><<<dim3(MID / 128,     ROWS_X / 128), 256, GEMM_SMEM>>>(xn, wtq2,  q,  ROWS_X, MID,     F, nullptr, nullptr);
    gemm_bf16<true ><<<dim3(2 * MID / 128, ROWS_C / 128), 256, GEMM_SMEM>>>(cn, wtkv2, kv, ROWS_C, 2 * MID, F, nullptr, nullptr);
    attn_bf16<<<dim3(NQ / 128, NHEAD, B), 256>>>(q, kv, ao, tbl + NHEAD * 4096, NQ, NCTX, NCTX - NQ);
    gemm_bf16<false><<<dim3(F / 128, ROWS_X / 128), 256, GEMM_SMEM>>>(ao, wto2, out, ROWS_X, F, MID, ca_bo, x1);
}